// round 15
// baseline (speedup 1.0000x reference)
#include <cuda_runtime.h>
#include <math_constants.h>
#include <cstdint>

// ChamferDistance: x1,x2 = [B=8, N=M=8192, 3] fp32.
// out = [ loss (1) | dist1 (B*N) | dist2 (B*M) ]
//
// R15: x-binned pruned NN using the PROVEN dense engine at proper granularity.
//  prep (R9, verified): zero/hist/prefix/scatter -> bin-grouped float4{x,y,z,idx}.
//  nn: 256 CTAs x 256 thr; CTA owns 512 bin-ordered A (PTS=2, packed f32x2).
//      Seed-scan B-slices (256 pts each) covering [amin,amax]; CTA-max bound
//      R = sqrt(max d)+margin; residual slices [amin-R, amax+R]. Inner loop =
//      R6 engine (packed-dup smem tiles, 3 FFMA2 + 2 FMNMX per k per jj).
//  Exact NN (superset argument, monotone bin fn) => deterministic.
//  Combine via int-punned atomicMin on 0x7F sentinel; 2-stage loss reduce.

constexpr int Bc = 8;
constexpr int Nc = 8192;
constexpr int NBINS = 256;
constexpr float XLO = -4.5f;
constexpr float INV_H = NBINS / 9.0f;
constexpr int NCB = 16;                        // cloud(2) * batch(8)
constexpr int NN_THREADS = 256;
constexpr int PTS = 2;                         // A-points per thread
constexpr int CHUNK_A = NN_THREADS * PTS;      // 512 A per CTA
constexpr int NN_GRID = NCB * (Nc / CHUNK_A);  // 256
constexpr int SLICE = 256;                     // B-points per slice
constexpr int JP = SLICE / 2;                  // 128 j-pairs
constexpr int NSLICES = Nc / SLICE;            // 32

__device__ float4 g_scat[NCB][Nc];
__device__ int g_cnt[NCB][NBINS];
__device__ int g_start[NCB][NBINS + 1];
__device__ int g_cur[NCB][NBINS];
__device__ float g_partials[128];

__device__ __forceinline__ unsigned long long pk2(float lo, float hi) {
    unsigned long long r;
    asm("mov.b64 %0, {%1, %2};" : "=l"(r) : "f"(lo), "f"(hi));
    return r;
}
__device__ __forceinline__ unsigned long long ffma2(unsigned long long a,
                                                    unsigned long long b,
                                                    unsigned long long c) {
    unsigned long long d;
    asm("fma.rn.f32x2 %0, %1, %2, %3;" : "=l"(d) : "l"(a), "l"(b), "l"(c));
    return d;
}
__device__ __forceinline__ void upk2(unsigned long long v, float& lo, float& hi) {
    asm("mov.b64 {%0, %1}, %2;" : "=f"(lo), "=f"(hi) : "l"(v));
}

__device__ __forceinline__ int bin_of(float x) {
    float v = (x - XLO) * INV_H;
    v = fminf(fmaxf(v, 0.0f), 255.0f);
    return (int)v;
}

// ---------------- binning kernels (verified in R9) ----------------

__global__ void __launch_bounds__(512) zero_kernel() {
    int* p = &g_cnt[0][0];
#pragma unroll
    for (int k = 0; k < 8; k++) p[k * 512 + threadIdx.x] = 0;
}

__global__ void __launch_bounds__(512)
hist_kernel(const float* __restrict__ x1, const float* __restrict__ x2) {
    const int gid = blockIdx.x * 512 + threadIdx.x;
    const int c = gid >> 16;
    const int r = gid & 65535;
    const int b = r >> 13;
    const int i = r & 8191;
    const float* src = c ? x2 : x1;
    const float x = src[((size_t)b * Nc + i) * 3];
    atomicAdd(&g_cnt[c * 8 + b][bin_of(x)], 1);
}

__global__ void __launch_bounds__(512) prefix_kernel() {
    const int cb = threadIdx.x >> 5;
    const int lane = threadIdx.x & 31;
    int cnt[8];
    int s = 0;
#pragma unroll
    for (int k = 0; k < 8; k++) { cnt[k] = g_cnt[cb][lane * 8 + k]; s += cnt[k]; }
    int run = s;
#pragma unroll
    for (int d = 1; d < 32; d <<= 1) {
        int v = __shfl_up_sync(0xffffffffu, run, d);
        if (lane >= d) run += v;
    }
    int excl = run - s;
#pragma unroll
    for (int k = 0; k < 8; k++) {
        g_start[cb][lane * 8 + k] = excl;
        g_cur[cb][lane * 8 + k] = excl;
        excl += cnt[k];
    }
    if (lane == 31) g_start[cb][NBINS] = excl;
}

__global__ void __launch_bounds__(512)
scatter_kernel(const float* __restrict__ x1, const float* __restrict__ x2) {
    const int gid = blockIdx.x * 512 + threadIdx.x;
    const int c = gid >> 16;
    const int r = gid & 65535;
    const int b = r >> 13;
    const int i = r & 8191;
    const float* src = c ? x2 : x1;
    const float* p = src + ((size_t)b * Nc + i) * 3;
    const float x = p[0], y = p[1], z = p[2];
    const int cb = c * 8 + b;
    const int pos = atomicAdd(&g_cur[cb][bin_of(x)], 1);
    g_scat[cb][pos] = make_float4(x, y, z, __int_as_float(i));
}

// ---------------- NN kernel ----------------

__global__ void __launch_bounds__(NN_THREADS, 4)
nn_kernel(float* __restrict__ dist1, float* __restrict__ dist2)
{
    __shared__ __align__(16) float tile[JP * 8];   // 4 KB packed-dup slice
    __shared__ float sred[NN_THREADS];

    const int tid = threadIdx.x;
    const int cbA = blockIdx.x >> 4;               // 16 chunks per (cloud,batch)
    const int seg = blockIdx.x & 15;
    const int cbB = cbA ^ 8;
    const int dir = cbA >> 3;
    const int b = cbA & 7;

    // load A: PTS=2 points per thread, coords duplicated into f32x2 halves
    unsigned long long axp[PTS], ayp[PTS], azp[PTS];
    float n1s[PTS];
    int oi[PTS];
    float myx_min = CUDART_INF_F, myx_max = -CUDART_INF_F;
#pragma unroll
    for (int k = 0; k < PTS; k++) {
        const float4 A = g_scat[cbA][seg * CHUNK_A + k * NN_THREADS + tid];
        axp[k] = pk2(A.x, A.x);
        ayp[k] = pk2(A.y, A.y);
        azp[k] = pk2(A.z, A.z);
        n1s[k] = fmaf(A.x, A.x, fmaf(A.y, A.y, A.z * A.z));
        oi[k] = __float_as_int(A.w);
        myx_min = fminf(myx_min, A.x);
        myx_max = fmaxf(myx_max, A.x);
    }

    // CTA amin/amax
    sred[tid] = myx_min;
    __syncthreads();
    for (int w = NN_THREADS / 2; w > 0; w >>= 1) {
        if (tid < w) sred[tid] = fminf(sred[tid], sred[tid + w]);
        __syncthreads();
    }
    const float amin = sred[0];
    __syncthreads();
    sred[tid] = myx_max;
    __syncthreads();
    for (int w = NN_THREADS / 2; w > 0; w >>= 1) {
        if (tid < w) sred[tid] = fmaxf(sred[tid], sred[tid + w]);
        __syncthreads();
    }
    const float amax = sred[0];
    __syncthreads();

    float eminE[PTS], eminO[PTS];
#pragma unroll
    for (int k = 0; k < PTS; k++) { eminE[k] = CUDART_INF_F; eminO[k] = CUDART_INF_F; }

    const float4* scatB = g_scat[cbB];

    // helper lambda-style slice scan (R6 engine)
    auto scan_slice = [&](int s) {
        __syncthreads();                           // protect previous tile
        if (tid < JP) {
            const float4 q0 = scatB[s * SLICE + 2 * tid];
            const float4 q1 = scatB[s * SLICE + 2 * tid + 1];
            const float n2e = fmaf(q0.x, q0.x, fmaf(q0.y, q0.y, q0.z * q0.z));
            const float n2o = fmaf(q1.x, q1.x, fmaf(q1.y, q1.y, q1.z * q1.z));
            float4* sm = reinterpret_cast<float4*>(&tile[tid * 8]);
            sm[0] = make_float4(-2.0f * q0.x, -2.0f * q1.x, -2.0f * q0.y, -2.0f * q1.y);
            sm[1] = make_float4(-2.0f * q0.z, -2.0f * q1.z, n2e, n2o);
        }
        __syncthreads();
        const ulonglong2* sp = reinterpret_cast<const ulonglong2*>(tile);
#pragma unroll 8
        for (int jj = 0; jj < JP; jj++) {
            const ulonglong2 c0 = sp[2 * jj];
            const ulonglong2 c1 = sp[2 * jj + 1];
#pragma unroll
            for (int k = 0; k < PTS; k++) {
                unsigned long long e = ffma2(axp[k], c0.x, c1.y);
                e = ffma2(ayp[k], c0.y, e);
                e = ffma2(azp[k], c1.x, e);
                float flo, fhi;
                upk2(e, flo, fhi);
                eminE[k] = fminf(eminE[k], flo);
                eminO[k] = fminf(eminO[k], fhi);
            }
        }
    };

    // seed: slices covering [amin, amax]
    const int* gs = g_start[cbB];
    int s0 = gs[bin_of(amin)] >> 8;
    int s1 = (gs[bin_of(amax) + 1] - 1) >> 8;
    s0 = max(min(s0, NSLICES - 1), 0);
    s1 = max(min(s1, NSLICES - 1), s0);
    for (int s = s0; s <= s1; s++) scan_slice(s);

    // bound
    float u = 0.0f;
#pragma unroll
    for (int k = 0; k < PTS; k++)
        u = fmaxf(u, n1s[k] + fminf(eminE[k], eminO[k]));
    sred[tid] = u;
    __syncthreads();
    for (int w = NN_THREADS / 2; w > 0; w >>= 1) {
        if (tid < w) sred[tid] = fmaxf(sred[tid], sred[tid + w]);
        __syncthreads();
    }
    const float R = sqrtf(fmaxf(sred[0], 0.0f)) * 1.0005f + 1e-3f;
    __syncthreads();

    // residual slices [f0, s0) and (s1, f1]
    int f0 = gs[bin_of(amin - R)] >> 8;
    int f1 = (gs[bin_of(amax + R) + 1] - 1) >> 8;
    f0 = max(min(f0, NSLICES - 1), 0);
    f1 = max(min(f1, NSLICES - 1), f0);
    for (int s = f0; s < s0; s++) scan_slice(s);
    for (int s = s1 + 1; s <= f1; s++) scan_slice(s);

    // flush (atomicMin combine; each A touched by exactly 1 CTA but keep the
    // proven sentinel+atomic path)
    float* __restrict__ outd = dir ? dist2 : dist1;
#pragma unroll
    for (int k = 0; k < PTS; k++) {
        const float d = fmaxf(n1s[k] + fminf(eminE[k], eminO[k]), 0.0f);
        atomicMin((int*)&outd[(size_t)b * Nc + oi[k]], __float_as_int(d));
    }
}

// ---------------- deterministic 2-stage loss reduction ----------------

__global__ void __launch_bounds__(256)
sum_stage1(const float* __restrict__ dists)
{
    __shared__ float red[256];
    const int tid = threadIdx.x;
    const int base = blockIdx.x * 1024;
    float s = 0.0f;
#pragma unroll
    for (int i = 0; i < 4; i++) s += dists[base + i * 256 + tid];
    red[tid] = s;
    __syncthreads();
    for (int w = 128; w > 0; w >>= 1) {
        if (tid < w) red[tid] += red[tid + w];
        __syncthreads();
    }
    if (tid == 0) g_partials[blockIdx.x] = red[0];
}

__global__ void __launch_bounds__(128)
sum_stage2(float* __restrict__ out)
{
    __shared__ float red[128];
    const int tid = threadIdx.x;
    red[tid] = g_partials[tid];
    __syncthreads();
    for (int w = 64; w > 0; w >>= 1) {
        if (tid < w) red[tid] += red[tid + w];
        __syncthreads();
    }
    if (tid == 0) out[0] = red[0] * (1.0f / (float)(Bc * Nc));
}

extern "C" void kernel_launch(void* const* d_in, const int* in_sizes, int n_in,
                              void* d_out, int out_size)
{
    const float* x1 = (const float*)d_in[0];
    const float* x2 = (const float*)d_in[1];
    float* out = (float*)d_out;
    float* dist1 = out + 1;
    float* dist2 = out + 1 + Bc * Nc;

    // Sentinel-fill dist arrays: 0x7F7F7F7F = 3.39e38 > any real sq-distance.
    cudaMemsetAsync(out + 1, 0x7F, (size_t)2 * Bc * Nc * sizeof(float));

    zero_kernel<<<1, 512>>>();
    hist_kernel<<<256, 512>>>(x1, x2);
    prefix_kernel<<<1, 512>>>();
    scatter_kernel<<<256, 512>>>(x1, x2);
    nn_kernel<<<NN_GRID, NN_THREADS>>>(dist1, dist2);

    sum_stage1<<<128, 256>>>(out + 1);
    sum_stage2<<<1, 128>>>(out);
}